// round 3
// baseline (speedup 1.0000x reference)
#include <cuda_runtime.h>
#include <cstdint>

// ---------------------------------------------------------------------------
// Problem constants
// ---------------------------------------------------------------------------
#define LEN_M   1088
#define D_H     64
#define M_PRI   65          // D_H + 1
#define M0      100
#define M1      100
#define NROWS   16384
#define DDIM    17          // DATA_DIM + 1
#define EPS0_N  (LEN_M * M0)            // 108800
#define EPS1_N  (M_PRI * M1)            // 6500
#define TAIL_N  (2*LEN_M + 2*M_PRI)     // 2306

// Scratch: sampled weights.
// g_W0t layout: [m][i] with i = d*64 + h  (contiguous per-m column block)
__device__ float g_W0t[M0 * LEN_M];
// g_W1 layout: [j][c], j in [0,65), c in [0,100)
__device__ float g_W1[M_PRI * M1];

// ---------------------------------------------------------------------------
// Threefry-2x32 (JAX-compatible), 20 rounds
// ---------------------------------------------------------------------------
__device__ __forceinline__ uint32_t rotl32(uint32_t v, int r) {
    return (v << r) | (v >> (32 - r));
}

__device__ __forceinline__ uint2 tf2x32(uint32_t k0, uint32_t k1,
                                        uint32_t x0, uint32_t x1) {
    uint32_t ks0 = k0, ks1 = k1, ks2 = k0 ^ k1 ^ 0x1BD11BDAu;
    x0 += ks0; x1 += ks1;
#define TF_R(r) { x0 += x1; x1 = rotl32(x1, r); x1 ^= x0; }
    TF_R(13) TF_R(15) TF_R(26) TF_R(6)   x0 += ks1; x1 += ks2 + 1u;
    TF_R(17) TF_R(29) TF_R(16) TF_R(24)  x0 += ks2; x1 += ks0 + 2u;
    TF_R(13) TF_R(15) TF_R(26) TF_R(6)   x0 += ks0; x1 += ks1 + 3u;
    TF_R(17) TF_R(29) TF_R(16) TF_R(24)  x0 += ks1; x1 += ks2 + 4u;
    TF_R(13) TF_R(15) TF_R(26) TF_R(6)   x0 += ks2; x1 += ks0 + 5u;
#undef TF_R
    return make_uint2(x0, x1);
}

// XLA ErfInv (single precision, Giles polynomial)
__device__ __forceinline__ float erfinv_xla(float x) {
    float w = -log1pf(-x * x);
    float p;
    if (w < 5.0f) {
        w -= 2.5f;
        p = 2.81022636e-08f;
        p = fmaf(p, w, 3.43273939e-07f);
        p = fmaf(p, w, -3.5233877e-06f);
        p = fmaf(p, w, -4.39150654e-06f);
        p = fmaf(p, w, 0.00021858087f);
        p = fmaf(p, w, -0.00125372503f);
        p = fmaf(p, w, -0.00417768164f);
        p = fmaf(p, w, 0.246640727f);
        p = fmaf(p, w, 1.50140941f);
    } else {
        w = sqrtf(w) - 3.0f;
        p = -0.000200214257f;
        p = fmaf(p, w, 0.000100950558f);
        p = fmaf(p, w, 0.00134934322f);
        p = fmaf(p, w, -0.00367342844f);
        p = fmaf(p, w, 0.00573950773f);
        p = fmaf(p, w, -0.0076224613f);
        p = fmaf(p, w, 0.00943887047f);
        p = fmaf(p, w, 1.00167406f);
        p = fmaf(p, w, 2.83297682f);
    }
    return p * x;
}

// JAX random.normal(key, ..., f32), partitionable path, element index -> value
__device__ __forceinline__ float jax_normal_bits(uint32_t bits) {
    const float LO = __uint_as_float(0xBF7FFFFFu);      // nextafter(-1, 0)
    float f = __uint_as_float((bits >> 9) | 0x3F800000u) - 1.0f;  // [0,1)
    float u = f * 2.0f + LO;                            // maxval-minval == 2.0f exactly
    u = fmaxf(u, LO);
    return 1.41421356237309515f * erfinv_xla(u);
}

// ---------------------------------------------------------------------------
// Gen kernel: sample W0 (transposed per-m), W1, and write tail outputs
// ---------------------------------------------------------------------------
__global__ void gen_kernel(const float* __restrict__ ms, float* __restrict__ out,
                           size_t tail_base) {
    int tid = blockIdx.x * blockDim.x + threadIdx.x;
    if (tid < EPS0_N) {
        // k0 = split(key(42))[0] = threefry((0,42), (0,0))
        uint2 k = tf2x32(0u, 42u, 0u, 0u);
        uint2 r = tf2x32(k.x, k.y, 0u, (uint32_t)tid);
        float eps = jax_normal_bits(r.x ^ r.y);
        int i = tid / M0;            // row in samps_w0 (= d*64+h)
        int m = tid - i * M0;
        float mean = ms[i];
        float var  = fabsf(ms[LEN_M + M_PRI + i]) + 1e-6f;
        g_W0t[m * LEN_M + i] = fmaf(eps, sqrtf(var), mean);
    } else if (tid < EPS0_N + EPS1_N) {
        int idx = tid - EPS0_N;
        // k1 = split(key(42))[1] = threefry((0,42), (0,1))
        uint2 k = tf2x32(0u, 42u, 0u, 1u);
        uint2 r = tf2x32(k.x, k.y, 0u, (uint32_t)idx);
        float eps = jax_normal_bits(r.x ^ r.y);
        int j = idx / M1;
        float mean = ms[LEN_M + j];
        float var  = fabsf(ms[2 * LEN_M + M_PRI + j]) + 1e-6f;
        g_W1[idx] = fmaf(eps, sqrtf(var), mean);
    } else if (tid < EPS0_N + EPS1_N + TAIL_N) {
        int o = tid - (EPS0_N + EPS1_N);
        float v;
        if (o < LEN_M)               v = ms[o];                                        // m_w0
        else if (o < 2 * LEN_M)      v = fabsf(ms[LEN_M + M_PRI + (o - LEN_M)]) + 1e-6f; // v_w0
        else if (o < 2 * LEN_M + M_PRI) v = ms[LEN_M + (o - 2 * LEN_M)];               // m_pri
        else                         v = fabsf(ms[2 * LEN_M + M_PRI + (o - 2 * LEN_M - M_PRI)]) + 1e-6f; // v_pri
        out[tail_base + o] = v;
    }
}

// ---------------------------------------------------------------------------
// Packed f32x2 helpers (FFMA2 path, sm_103a)
// ---------------------------------------------------------------------------
typedef unsigned long long u64;

__device__ __forceinline__ u64 pk2(float a, float b) {
    u64 r;
    asm("mov.b64 %0, {%1, %2};" : "=l"(r) : "f"(a), "f"(b));
    return r;
}
__device__ __forceinline__ void upk2(u64 v, float& a, float& b) {
    asm("mov.b64 {%0, %1}, %2;" : "=f"(a), "=f"(b) : "l"(v));
}
__device__ __forceinline__ u64 fma2(u64 a, u64 b, u64 c) {
    u64 d;
    asm("fma.rn.f32x2 %0, %1, %2, %3;" : "=l"(d) : "l"(a), "l"(b), "l"(c));
    return d;
}
__device__ __forceinline__ u64 add2(u64 a, u64 b) {
    u64 d;
    asm("add.rn.f32x2 %0, %1, %2;" : "=l"(d) : "l"(a), "l"(b));
    return d;
}

// ---------------------------------------------------------------------------
// Main kernel: one thread per (n, m); 100 c-accumulators as 50 f32x2 regs.
// Block = 256 n's, blockIdx.y = m.
// ---------------------------------------------------------------------------
__global__ void __launch_bounds__(256, 1)
pred_kernel(const float* __restrict__ x, float* __restrict__ out) {
    __shared__ float sW0[LEN_M];       // W0t column for this m: [d*64 + h]
    __shared__ float sW1[M_PRI * M1];  // [j][c]

    const int m   = blockIdx.y;
    const int tid = threadIdx.x;

    for (int i = tid; i < M_PRI * M1; i += 256) sW1[i] = g_W1[i];
    for (int i = tid; i < LEN_M; i += 256)      sW0[i] = g_W0t[m * LEN_M + i];

    const int n = blockIdx.x * 256 + tid;
    const float* xr = x + (size_t)n * DDIM;
    u64 xd[DDIM];
#pragma unroll
    for (int d = 0; d < DDIM; ++d) { float v = xr[d]; xd[d] = pk2(v, v); }

    __syncthreads();

    // init accumulators with bias row W1[0][:]
    u64 acc[50];
    {
        const ulonglong2* b = reinterpret_cast<const ulonglong2*>(sW1);
#pragma unroll
        for (int q = 0; q < 25; ++q) {
            ulonglong2 bv = b[q];
            acc[2 * q]     = bv.x;
            acc[2 * q + 1] = bv.y;
        }
    }

#pragma unroll 1
    for (int h = 0; h < D_H; h += 2) {
        // z for hidden units h and h+1 (packed), 17-term dot with x
        u64 zz0 = 0ull, zz1 = 0ull;
#pragma unroll
        for (int d = 0; d < 16; d += 2) {
            zz0 = fma2(xd[d],     *reinterpret_cast<const u64*>(&sW0[d * D_H + h]),       zz0);
            zz1 = fma2(xd[d + 1], *reinterpret_cast<const u64*>(&sW0[(d + 1) * D_H + h]), zz1);
        }
        zz0 = fma2(xd[16], *reinterpret_cast<const u64*>(&sW0[16 * D_H + h]), zz0);
        zz0 = add2(zz0, zz1);

        float za, zb;
        upk2(zz0, za, zb);
        za = fmaxf(za, 0.0f);
        zb = fmaxf(zb, 0.0f);
        u64 za2 = pk2(za, za);
        u64 zb2 = pk2(zb, zb);

        const ulonglong2* w1a = reinterpret_cast<const ulonglong2*>(sW1 + (h + 1) * M1);
        const ulonglong2* w1b = reinterpret_cast<const ulonglong2*>(sW1 + (h + 2) * M1);
#pragma unroll
        for (int q = 0; q < 25; ++q) {
            ulonglong2 wa = w1a[q];
            ulonglong2 wb = w1b[q];
            acc[2 * q]     = fma2(za2, wa.x, acc[2 * q]);
            acc[2 * q + 1] = fma2(za2, wa.y, acc[2 * q + 1]);
            acc[2 * q]     = fma2(zb2, wb.x, acc[2 * q]);
            acc[2 * q + 1] = fma2(zb2, wb.y, acc[2 * q + 1]);
        }
    }

    // store pred[n][m][0..99]
    float* o = out + ((size_t)n * M0 + m) * M1;
#pragma unroll
    for (int q = 0; q < 25; ++q) {
        float a0, a1, a2, a3;
        upk2(acc[2 * q],     a0, a1);
        upk2(acc[2 * q + 1], a2, a3);
        float4 v = make_float4(a0, a1, a2, a3);
        *reinterpret_cast<float4*>(o + 4 * q) = v;
    }
}

// ---------------------------------------------------------------------------
// kernel_launch
// ---------------------------------------------------------------------------
extern "C" void kernel_launch(void* const* d_in, const int* in_sizes, int n_in,
                              void* d_out, int out_size) {
    const float* x  = (const float*)d_in[0];
    const float* ms = (const float*)d_in[1];
    // defensive: identify inputs by size
    if (n_in >= 2 && in_sizes[0] == TAIL_N) {
        ms = (const float*)d_in[0];
        x  = (const float*)d_in[1];
    }
    float* out = (float*)d_out;
    size_t tail_base = (size_t)out_size - TAIL_N;

    {
        int total = EPS0_N + EPS1_N + TAIL_N;
        gen_kernel<<<(total + 255) / 256, 256>>>(ms, out, tail_base);
    }
    {
        dim3 grid(NROWS / 256, M0);
        pred_kernel<<<grid, 256>>>(x, out);
    }
}

// round 4
// speedup vs baseline: 1.6803x; 1.6803x over previous
#include <cuda_runtime.h>
#include <cstdint>

// ---------------------------------------------------------------------------
// Problem constants
// ---------------------------------------------------------------------------
#define LEN_M   1088
#define D_H     64
#define M_PRI   65          // D_H + 1
#define M0      100
#define M1      100
#define NROWS   16384
#define DDIM    17          // DATA_DIM + 1
#define EPS0_N  (LEN_M * M0)            // 108800
#define EPS1_N  (M_PRI * M1)            // 6500
#define TAIL_N  (2*LEN_M + 2*M_PRI)     // 2306

#define NT      64          // n-tile per block
#define ZSTRIDE 66          // padded row stride for sZ (floats)

// Scratch: sampled weights.
// g_W0t layout: [m][i] with i = d*64 + h  (contiguous per-m column block)
__device__ float g_W0t[M0 * LEN_M];
// g_W1 layout: [j][c], j in [0,65), c in [0,100)
__device__ float g_W1[M_PRI * M1];

// ---------------------------------------------------------------------------
// Threefry-2x32 (JAX-compatible), 20 rounds
// ---------------------------------------------------------------------------
__device__ __forceinline__ uint32_t rotl32(uint32_t v, int r) {
    return (v << r) | (v >> (32 - r));
}

__device__ __forceinline__ uint2 tf2x32(uint32_t k0, uint32_t k1,
                                        uint32_t x0, uint32_t x1) {
    uint32_t ks0 = k0, ks1 = k1, ks2 = k0 ^ k1 ^ 0x1BD11BDAu;
    x0 += ks0; x1 += ks1;
#define TF_R(r) { x0 += x1; x1 = rotl32(x1, r); x1 ^= x0; }
    TF_R(13) TF_R(15) TF_R(26) TF_R(6)   x0 += ks1; x1 += ks2 + 1u;
    TF_R(17) TF_R(29) TF_R(16) TF_R(24)  x0 += ks2; x1 += ks0 + 2u;
    TF_R(13) TF_R(15) TF_R(26) TF_R(6)   x0 += ks0; x1 += ks1 + 3u;
    TF_R(17) TF_R(29) TF_R(16) TF_R(24)  x0 += ks1; x1 += ks2 + 4u;
    TF_R(13) TF_R(15) TF_R(26) TF_R(6)   x0 += ks2; x1 += ks0 + 5u;
#undef TF_R
    return make_uint2(x0, x1);
}

// XLA ErfInv (single precision, Giles polynomial)
__device__ __forceinline__ float erfinv_xla(float x) {
    float w = -log1pf(-x * x);
    float p;
    if (w < 5.0f) {
        w -= 2.5f;
        p = 2.81022636e-08f;
        p = fmaf(p, w, 3.43273939e-07f);
        p = fmaf(p, w, -3.5233877e-06f);
        p = fmaf(p, w, -4.39150654e-06f);
        p = fmaf(p, w, 0.00021858087f);
        p = fmaf(p, w, -0.00125372503f);
        p = fmaf(p, w, -0.00417768164f);
        p = fmaf(p, w, 0.246640727f);
        p = fmaf(p, w, 1.50140941f);
    } else {
        w = sqrtf(w) - 3.0f;
        p = -0.000200214257f;
        p = fmaf(p, w, 0.000100950558f);
        p = fmaf(p, w, 0.00134934322f);
        p = fmaf(p, w, -0.00367342844f);
        p = fmaf(p, w, 0.00573950773f);
        p = fmaf(p, w, -0.0076224613f);
        p = fmaf(p, w, 0.00943887047f);
        p = fmaf(p, w, 1.00167406f);
        p = fmaf(p, w, 2.83297682f);
    }
    return p * x;
}

// JAX random.normal(key, ..., f32), partitionable path, element index -> value
__device__ __forceinline__ float jax_normal_bits(uint32_t bits) {
    const float LO = __uint_as_float(0xBF7FFFFFu);      // nextafter(-1, 0)
    float f = __uint_as_float((bits >> 9) | 0x3F800000u) - 1.0f;  // [0,1)
    float u = f * 2.0f + LO;                            // maxval-minval == 2.0f exactly
    u = fmaxf(u, LO);
    return 1.41421356237309515f * erfinv_xla(u);
}

// ---------------------------------------------------------------------------
// Gen kernel: sample W0 (transposed per-m), W1, and write tail outputs
// ---------------------------------------------------------------------------
__global__ void gen_kernel(const float* __restrict__ ms, float* __restrict__ out,
                           size_t tail_base) {
    int tid = blockIdx.x * blockDim.x + threadIdx.x;
    if (tid < EPS0_N) {
        // k0 = split(key(42))[0] = threefry((0,42), (0,0))
        uint2 k = tf2x32(0u, 42u, 0u, 0u);
        uint2 r = tf2x32(k.x, k.y, 0u, (uint32_t)tid);
        float eps = jax_normal_bits(r.x ^ r.y);
        int i = tid / M0;            // row in samps_w0 (= d*64+h)
        int m = tid - i * M0;
        float mean = ms[i];
        float var  = fabsf(ms[LEN_M + M_PRI + i]) + 1e-6f;
        g_W0t[m * LEN_M + i] = fmaf(eps, sqrtf(var), mean);
    } else if (tid < EPS0_N + EPS1_N) {
        int idx = tid - EPS0_N;
        // k1 = split(key(42))[1] = threefry((0,42), (0,1))
        uint2 k = tf2x32(0u, 42u, 0u, 1u);
        uint2 r = tf2x32(k.x, k.y, 0u, (uint32_t)idx);
        float eps = jax_normal_bits(r.x ^ r.y);
        int j = idx / M1;
        float mean = ms[LEN_M + j];
        float var  = fabsf(ms[2 * LEN_M + M_PRI + j]) + 1e-6f;
        g_W1[idx] = fmaf(eps, sqrtf(var), mean);
    } else if (tid < EPS0_N + EPS1_N + TAIL_N) {
        int o = tid - (EPS0_N + EPS1_N);
        float v;
        if (o < LEN_M)               v = ms[o];                                        // m_w0
        else if (o < 2 * LEN_M)      v = fabsf(ms[LEN_M + M_PRI + (o - LEN_M)]) + 1e-6f; // v_w0
        else if (o < 2 * LEN_M + M_PRI) v = ms[LEN_M + (o - 2 * LEN_M)];               // m_pri
        else                         v = fabsf(ms[2 * LEN_M + M_PRI + (o - 2 * LEN_M - M_PRI)]) + 1e-6f; // v_pri
        out[tail_base + o] = v;
    }
}

// ---------------------------------------------------------------------------
// Packed f32x2 helpers (FFMA2 path, sm_103a)
// ---------------------------------------------------------------------------
typedef unsigned long long u64;

__device__ __forceinline__ u64 pk2(float a, float b) {
    u64 r;
    asm("mov.b64 %0, {%1, %2};" : "=l"(r) : "f"(a), "f"(b));
    return r;
}
__device__ __forceinline__ void upk2(u64 v, float& a, float& b) {
    asm("mov.b64 {%0, %1}, %2;" : "=f"(a), "=f"(b) : "l"(v));
}
__device__ __forceinline__ u64 fma2(u64 a, u64 b, u64 c) {
    u64 d;
    asm("fma.rn.f32x2 %0, %1, %2, %3;" : "=l"(d) : "l"(a), "l"(b), "l"(c));
    return d;
}

// ---------------------------------------------------------------------------
// Main kernel: block = (m, 64-row n-tile), 128 threads.
// Phase A: Z[64h x 64n] into smem (layer 1 + relu, computed once per tile).
// Phase B: per-thread 2n x 26c register tile; W1 rows streamed from smem and
//          shared across both n's; FFMA2 is the dominant instruction.
// ---------------------------------------------------------------------------
__global__ void __launch_bounds__(128, 4)
pred_kernel(const float* __restrict__ x, float* __restrict__ out) {
    __shared__ __align__(16) float sW0[LEN_M];            //  4.25 KB
    __shared__ __align__(16) float sW1[M_PRI * M1 + 8];   // 25.4  KB (padded)
    __shared__ __align__(16) float sZ[D_H * ZSTRIDE];     // 16.5  KB

    const int tid   = threadIdx.x;
    const int m     = blockIdx.y;
    const int nbase = blockIdx.x * NT;

    for (int i = tid; i < M_PRI * M1 + 8; i += 128)
        sW1[i] = (i < M_PRI * M1) ? g_W1[i] : 0.0f;
    for (int i = tid; i < LEN_M; i += 128)
        sW0[i] = g_W0t[m * LEN_M + i];

    // ---- load x row into registers (2 threads per n-row) ----
    const int n_loc = tid >> 1;            // 0..63
    const int hbase = (tid & 1) * 32;      // 0 or 32
    const float* xr = x + (size_t)(nbase + n_loc) * DDIM;
    u64 xd[DDIM];
#pragma unroll
    for (int d = 0; d < DDIM; ++d) { float v = __ldg(xr + d); xd[d] = pk2(v, v); }

    __syncthreads();

    // ---- Phase A: hidden layer, 32 h's per thread, h packed in pairs ----
#pragma unroll 4
    for (int hp = 0; hp < 16; ++hp) {
        const int h = hbase + 2 * hp;
        u64 zz = 0ull;
#pragma unroll
        for (int d = 0; d < DDIM; ++d)
            zz = fma2(xd[d], *reinterpret_cast<const u64*>(&sW0[d * D_H + h]), zz);
        float za, zb;
        upk2(zz, za, zb);
        sZ[h * ZSTRIDE + n_loc]       = fmaxf(za, 0.0f);
        sZ[(h + 1) * ZSTRIDE + n_loc] = fmaxf(zb, 0.0f);
    }
    __syncthreads();

    // ---- Phase B: 2 n's x 26 c's per thread (c-groups at 0/26/52/78) ----
    const int np   = tid >> 2;             // 0..31 -> n pair
    const int cg   = tid & 3;              // 0..3  -> c group
    const int coff = cg * 26;
    const float* w1 = sW1 + coff;

    u64 acc0[13], acc1[13];
#pragma unroll
    for (int j = 0; j < 13; ++j) {
        u64 w = *reinterpret_cast<const u64*>(w1 + 2 * j);   // bias row W1[0][:]
        acc0[j] = w;
        acc1[j] = w;
    }

#pragma unroll 2
    for (int h = 0; h < D_H; ++h) {
        const float za = sZ[h * ZSTRIDE + 2 * np];
        const float zb = sZ[h * ZSTRIDE + 2 * np + 1];
        const u64 za2 = pk2(za, za);
        const u64 zb2 = pk2(zb, zb);
        const float* wr = w1 + (h + 1) * M1;
#pragma unroll
        for (int j = 0; j < 13; ++j) {
            u64 w = *reinterpret_cast<const u64*>(wr + 2 * j);
            acc0[j] = fma2(za2, w, acc0[j]);
            acc1[j] = fma2(zb2, w, acc1[j]);
        }
    }

    // ---- store: out[n][m][c], 8-byte stores, group 3 covers c 78..99 ----
    const int n0 = nbase + 2 * np;
    float* o0 = out + ((size_t)n0 * M0 + m) * M1 + coff;
    float* o1 = o0 + (size_t)M0 * M1;
    const int jmax = (cg == 3) ? 11 : 13;
#pragma unroll
    for (int j = 0; j < 13; ++j) {
        if (j < jmax) {
            *reinterpret_cast<u64*>(o0 + 2 * j) = acc0[j];
            *reinterpret_cast<u64*>(o1 + 2 * j) = acc1[j];
        }
    }
}

// ---------------------------------------------------------------------------
// kernel_launch
// ---------------------------------------------------------------------------
extern "C" void kernel_launch(void* const* d_in, const int* in_sizes, int n_in,
                              void* d_out, int out_size) {
    const float* x  = (const float*)d_in[0];
    const float* ms = (const float*)d_in[1];
    // defensive: identify inputs by size
    if (n_in >= 2 && in_sizes[0] == TAIL_N) {
        ms = (const float*)d_in[0];
        x  = (const float*)d_in[1];
    }
    float* out = (float*)d_out;
    size_t tail_base = (size_t)out_size - TAIL_N;

    {
        int total = EPS0_N + EPS1_N + TAIL_N;
        gen_kernel<<<(total + 255) / 256, 256>>>(ms, out, tail_base);
    }
    {
        dim3 grid(NROWS / NT, M0);
        pred_kernel<<<grid, 128>>>(x, out);
    }
}